// round 1
// baseline (speedup 1.0000x reference)
#include <cuda_runtime.h>
#include <cuda_bf16.h>

#define N_NODES_MAX 100000

__device__ float g_Z[N_NODES_MAX];
__device__ float g_Z23[N_NODES_MAX];

// ---------------- node prep: Z = one_hot @ atomic_numbers, Z23 = Z^0.23 ----------
__global__ void node_prep_kernel(const float* __restrict__ attrs,
                                 const float* __restrict__ atomic_numbers,
                                 int n_nodes, int n_elem) {
    int i = blockIdx.x * blockDim.x + threadIdx.x;
    if (i >= n_nodes) return;
    float z = 0.f;
    for (int k = 0; k < n_elem; k++)
        z += attrs[i * n_elem + k] * atomic_numbers[k];
    g_Z[i] = z;
    g_Z23[i] = powf(z, 0.23f);
}

// ---------------- zero output --------------------------------------------------
__global__ void zero_kernel(float* __restrict__ out, int n) {
    int i = blockIdx.x * blockDim.x + threadIdx.x;
    if (i < n) out[i] = 0.f;
}

// ---------------- edge kernel --------------------------------------------------
__global__ void edge_kernel(const float* __restrict__ lengths,
                            const int* __restrict__ edge_index,
                            const float* __restrict__ rmax_ptr,
                            float* __restrict__ out,
                            int n_edges) {
    const float KE = 14.3996454784255f;
    const float A0 = 0.52917721092f;
    const float ZA0 = 0.1818f, ZA1 = 0.5099f, ZA2 = 0.2802f, ZA3 = 0.02817f;
    const float ZB0 = 3.2f,    ZB1 = 0.9423f, ZB2 = 0.4029f, ZB3 = 0.2016f;

    const float r_max = *rmax_ptr;
    const float inv_rmax = 1.f / r_max;

    int e = blockIdx.x * blockDim.x + threadIdx.x;
    if (e >= n_edges) return;

    int src = edge_index[e];
    int dst = edge_index[n_edges + e];

    float r = fmaxf(lengths[e], 0.2f);

    float zi  = g_Z[src];
    float zj  = g_Z[dst];
    float z23 = g_Z23[src] + g_Z23[dst];

    // ZBL
    float a   = 0.88534f * A0 / z23;
    float x   = r / a;
    float phi = ZA0 * __expf(-ZB0 * x) + ZA1 * __expf(-ZB1 * x)
              + ZA2 * __expf(-ZB2 * x) + ZA3 * __expf(-ZB3 * x);

    // poly cutoff (1 - clip(r/rmax,0,1))^6
    float xc  = fminf(r * inv_rmax, 1.f);
    float om  = 1.f - xc;
    float om2 = om * om;
    float cut = om2 * om2 * om2;

    float Vzbl = KE * zi * zj * (phi / r) * cut;

    // r12 term
    float r2  = r * r;
    float r4  = r2 * r2;
    float r12 = r4 * r4 * r4;
    float t   = fminf(fmaxf((1.5f - r) * 5.0f, 0.f), 1.f);   // /0.2
    float sm  = t * t * (3.f - 2.f * t);
    float V12 = (1e-4f / r12) * cut * sm;

    float quarter = 0.25f * (Vzbl + V12);

    atomicAdd(&out[src], quarter);
    atomicAdd(&out[dst], quarter);
}

// ---------------- launch --------------------------------------------------------
extern "C" void kernel_launch(void* const* d_in, const int* in_sizes, int n_in,
                              void* d_out, int out_size) {
    const float* lengths        = (const float*)d_in[0];
    const float* node_attrs     = (const float*)d_in[1];
    const int*   edge_index     = (const int*)d_in[2];
    const float* atomic_numbers = (const float*)d_in[3];
    const float* r_max          = (const float*)d_in[4];

    float* out = (float*)d_out;

    int n_edges = in_sizes[0];
    int n_elem  = in_sizes[3];
    int n_nodes = in_sizes[1] / n_elem;

    node_prep_kernel<<<(n_nodes + 255) / 256, 256>>>(node_attrs, atomic_numbers,
                                                     n_nodes, n_elem);
    zero_kernel<<<(out_size + 255) / 256, 256>>>(out, out_size);
    edge_kernel<<<(n_edges + 255) / 256, 256>>>(lengths, edge_index, r_max,
                                                out, n_edges);
}

// round 2
// speedup vs baseline: 1.6983x; 1.6983x over previous
#include <cuda_runtime.h>
#include <cuda_bf16.h>

#define N_NODES_MAX 100000

__device__ unsigned char g_spec[N_NODES_MAX];

// ---------------- node prep: species id from one-hot ---------------------------
__global__ void node_prep_kernel(const float* __restrict__ attrs,
                                 int n_nodes, int n_elem) {
    int i = blockIdx.x * blockDim.x + threadIdx.x;
    if (i >= n_nodes) return;
    float s = 0.f;
    for (int k = 0; k < n_elem; k++)
        s += (float)k * attrs[i * n_elem + k];
    g_spec[i] = (unsigned char)(s + 0.5f);
}

// ---------------- zero output --------------------------------------------------
__global__ void zero_kernel(float* __restrict__ out, int n) {
    int i = blockIdx.x * blockDim.x + threadIdx.x;
    if (i < n) out[i] = 0.f;
}

// ---------------- edge kernel --------------------------------------------------
// 4 edges per thread, vectorized coalesced loads, byte species gathers,
// 100-entry shared pair table (c = 0.25*KE*Zi*Zj, inv_a = (Zi^.23+Zj^.23)/(0.88534*a0))
#define EPT 4

__global__ __launch_bounds__(256) void edge_kernel(
        const float4* __restrict__ lengths4,
        const int4* __restrict__ src4,
        const int4* __restrict__ dst4,
        const float* __restrict__ atomic_numbers,
        const float* __restrict__ rmax_ptr,
        float* __restrict__ out,
        int n_edges, int n_elem) {

    __shared__ float2 pairTab[128];   // [si*n_elem+sj] -> (c, inv_a)

    const float KE = 14.3996454784255f;
    const float A0 = 0.52917721092f;

    int npair = n_elem * n_elem;
    for (int i = threadIdx.x; i < npair; i += blockDim.x) {
        int si = i / n_elem, sj = i % n_elem;
        float Zi = atomic_numbers[si];
        float Zj = atomic_numbers[sj];
        float c = 0.25f * KE * Zi * Zj;                          // SCALE=1
        float inv_a = (powf(Zi, 0.23f) + powf(Zj, 0.23f)) / (0.88534f * A0);
        pairTab[i] = make_float2(c, inv_a);
    }
    __syncthreads();

    const float r_max = *rmax_ptr;
    const float inv_rmax = 1.f / r_max;

    const float ZA0 = 0.1818f, ZA1 = 0.5099f, ZA2 = 0.2802f, ZA3 = 0.02817f;
    const float ZB0 = 3.2f,    ZB1 = 0.9423f, ZB2 = 0.4029f, ZB3 = 0.2016f;

    int nq = n_edges / EPT;   // n_edges assumed divisible by 4 (6.4M); guarded below
    int q = blockIdx.x * blockDim.x + threadIdx.x;
    if (q < nq) {
        float4 rv = lengths4[q];
        int4   sv = src4[q];
        int4   dv = dst4[q];

        float rr[EPT] = {rv.x, rv.y, rv.z, rv.w};
        int   ss[EPT] = {sv.x, sv.y, sv.z, sv.w};
        int   dd[EPT] = {dv.x, dv.y, dv.z, dv.w};

        int spi[EPT], spj[EPT];
        #pragma unroll
        for (int k = 0; k < EPT; k++) spi[k] = g_spec[ss[k]];
        #pragma unroll
        for (int k = 0; k < EPT; k++) spj[k] = g_spec[dd[k]];

        #pragma unroll
        for (int k = 0; k < EPT; k++) {
            float r = fmaxf(rr[k], 0.2f);
            float2 pt = pairTab[spi[k] * n_elem + spj[k]];

            float x   = r * pt.y;
            float phi = ZA0 * __expf(-ZB0 * x) + ZA1 * __expf(-ZB1 * x)
                      + ZA2 * __expf(-ZB2 * x) + ZA3 * __expf(-ZB3 * x);

            float xc  = fminf(r * inv_rmax, 1.f);
            float om  = 1.f - xc;
            float om2 = om * om;
            float cut = om2 * om2 * om2;

            float Vzbl = pt.x * (phi / r) * cut;       // already *0.25

            float r2  = r * r;
            float r4  = r2 * r2;
            float r12 = r4 * r4 * r4;
            float t   = fminf(fmaxf((1.5f - r) * 5.0f, 0.f), 1.f);
            float sm  = t * t * (3.f - 2.f * t);
            float V12 = (2.5e-5f / r12) * cut * sm;    // 0.25 * 1e-4

            float quarter = Vzbl + V12;

            atomicAdd(&out[ss[k]], quarter);
            atomicAdd(&out[dd[k]], quarter);
        }
    }

    // tail (n_edges not multiple of 4) — handled by last thread of grid
    if (q == 0) {
        const float* lengths = (const float*)lengths4;
        const int* src = (const int*)src4;
        const int* dst = (const int*)dst4;
        for (int e = nq * EPT; e < n_edges; e++) {
            float r = fmaxf(lengths[e], 0.2f);
            int si = g_spec[src[e]], sj = g_spec[dst[e]];
            float2 pt = pairTab[si * n_elem + sj];
            float x   = r * pt.y;
            float phi = ZA0 * __expf(-ZB0 * x) + ZA1 * __expf(-ZB1 * x)
                      + ZA2 * __expf(-ZB2 * x) + ZA3 * __expf(-ZB3 * x);
            float xc  = fminf(r * inv_rmax, 1.f);
            float om  = 1.f - xc;
            float om2 = om * om;
            float cut = om2 * om2 * om2;
            float Vzbl = pt.x * (phi / r) * cut;
            float r2  = r * r;
            float r4  = r2 * r2;
            float r12 = r4 * r4 * r4;
            float t   = fminf(fmaxf((1.5f - r) * 5.0f, 0.f), 1.f);
            float sm  = t * t * (3.f - 2.f * t);
            float V12 = (2.5e-5f / r12) * cut * sm;
            float quarter = Vzbl + V12;
            atomicAdd(&out[src[e]], quarter);
            atomicAdd(&out[dst[e]], quarter);
        }
    }
}

// ---------------- launch --------------------------------------------------------
extern "C" void kernel_launch(void* const* d_in, const int* in_sizes, int n_in,
                              void* d_out, int out_size) {
    const float* lengths        = (const float*)d_in[0];
    const float* node_attrs     = (const float*)d_in[1];
    const int*   edge_index     = (const int*)d_in[2];
    const float* atomic_numbers = (const float*)d_in[3];
    const float* r_max          = (const float*)d_in[4];

    float* out = (float*)d_out;

    int n_edges = in_sizes[0];
    int n_elem  = in_sizes[3];
    int n_nodes = in_sizes[1] / n_elem;

    node_prep_kernel<<<(n_nodes + 255) / 256, 256>>>(node_attrs, n_nodes, n_elem);
    zero_kernel<<<(out_size + 255) / 256, 256>>>(out, out_size);

    int nq = n_edges / EPT;
    int blocks = (nq + 255) / 256;
    if (blocks < 1) blocks = 1;
    edge_kernel<<<blocks, 256>>>((const float4*)lengths,
                                 (const int4*)edge_index,
                                 (const int4*)(edge_index + n_edges),
                                 atomic_numbers, r_max, out,
                                 n_edges, n_elem);
}